// round 6
// baseline (speedup 1.0000x reference)
#include <cuda_runtime.h>
#include <climits>

// Problem constants
#define BB 64
#define PP 5000
#define GG 300
#define NC 20
#define SPLIT 10          // chunks per image in the main kernel
#define THREADS 256

// Scratch (device globals -- no allocation allowed)
__device__ int   g_winner[BB * GG];   // min pred index claiming each target
__device__ short g_bi[BB * PP];       // best target per pred, -1 if no candidate

// ---------------------------------------------------------------------------
// Kernel 1: reset winners + write tcls output tail
// out layout assumed: stats (B,P,3) fp32 followed by tcls (B,G) fp32
// ---------------------------------------------------------------------------
__global__ void mbe_init_kernel(const float* __restrict__ labels,
                                float* __restrict__ out_tcls) {
    int i = blockIdx.x * blockDim.x + threadIdx.x;
    if (i < BB * GG) {
        g_winner[i] = INT_MAX;
        out_tcls[i] = labels[i * 5 + 4];   // labels[(b*G+g)*5 + 4]
    }
}

// ---------------------------------------------------------------------------
// Kernel 2: per-pred best-target search with class-bucketed targets.
// grid.x = BB * SPLIT ; each block handles P/SPLIT preds of one image.
// ---------------------------------------------------------------------------
__global__ __launch_bounds__(THREADS)
void mbe_main_kernel(const float* __restrict__ preds,
                     const float* __restrict__ labels,
                     float* __restrict__ stats) {
    __shared__ float  s_lab[GG * 5];
    __shared__ float4 s_tbox[GG];      // scaled (x1,y1,x2,y2), sorted by class
    __shared__ float  s_tarea[GG];
    __shared__ int    s_start[NC + 1];
    __shared__ int    s_cnt[NC];

    const int b     = blockIdx.x / SPLIT;
    const int chunk = blockIdx.x % SPLIT;
    const int tid   = threadIdx.x;

    // Stage labels for this image
    const float* lab = labels + (long)b * GG * 5;
    for (int i = tid; i < GG * 5; i += THREADS) s_lab[i] = lab[i];
    if (tid < NC) s_cnt[tid] = 0;
    __syncthreads();

    // Class histogram
    for (int g = tid; g < GG; g += THREADS) {
        int c = (int)s_lab[g * 5 + 4];
        if ((unsigned)c < NC) atomicAdd(&s_cnt[c], 1);
    }
    __syncthreads();

    if (tid == 0) {
        int acc = 0;
        for (int c = 0; c < NC; c++) { s_start[c] = acc; acc += s_cnt[c]; }
        s_start[NC] = acc;
    }
    __syncthreads();

    // Stable counting-sort placement: one thread per class walks targets in
    // original order -> within-class original order preserved (argmax ties).
    if (tid < NC) {
        int pos = s_start[tid];
        for (int g = 0; g < GG; g++) {
            if ((int)s_lab[g * 5 + 4] == tid) {
                float x1 = s_lab[g * 5 + 0] * 512.0f;
                float y1 = s_lab[g * 5 + 1] * 512.0f;
                float x2 = s_lab[g * 5 + 2] * 512.0f;
                float y2 = s_lab[g * 5 + 3] * 512.0f;
                s_tbox[pos]  = make_float4(x1, y1, x2, y2);
                s_tarea[pos] = (x2 - x1) * (y2 - y1);
                pos++;
            }
        }
    }
    __syncthreads();

    const int winner_base = b * GG;
    const int pper = (PP + SPLIT - 1) / SPLIT;
    const int p0 = chunk * pper;
    const int p1 = (p0 + pper < PP) ? (p0 + pper) : PP;

    for (int p = p0 + tid; p < p1; p += THREADS) {
        const float* pr = preds + ((long)b * PP + p) * 6;
        float2 q0 = *(const float2*)(pr);       // x1, y1
        float2 q1 = *(const float2*)(pr + 2);   // x2, y2
        float2 q2 = *(const float2*)(pr + 4);   // score, cls

        float px1 = q0.x * 512.0f, py1 = q0.y * 512.0f;
        float px2 = q1.x * 512.0f, py2 = q1.y * 512.0f;
        float score = q2.x;
        float fcls  = q2.y;
        float parea = (px2 - px1) * (py2 - py1);
        int cls = (int)fcls;

        int   bi   = -1;
        float best = 0.5f;   // = IOU_THRESH: only > thresh targets can win

        if ((unsigned)cls < NC && score > 0.0f) {
            int t0 = s_start[cls], t1 = s_start[cls + 1];
            for (int t = t0; t < t1; t++) {
                float4 tb = s_tbox[t];
                float lx = fmaxf(px1, tb.x);
                float ly = fmaxf(py1, tb.y);
                float rx = fminf(px2, tb.z);
                float ry = fminf(py2, tb.w);
                float w = fmaxf(rx - lx, 0.0f);
                float h = fmaxf(ry - ly, 0.0f);
                float inter = w * h;
                if (inter > 0.0f) {
                    float denom = (parea + s_tarea[t]) - inter;  // ref op order
                    float iou = __fdiv_rn(inter, denom);          // IEEE div
                    if (iou > best) { best = iou; bi = t; }       // first-max
                }
            }
        }

        g_bi[b * PP + p] = (short)bi;
        if (bi >= 0) atomicMin(&g_winner[winner_base + bi], p);

        long o = ((long)b * PP + p) * 3;
        stats[o + 1] = score;
        stats[o + 2] = fcls;
    }
}

// ---------------------------------------------------------------------------
// Kernel 3: winner check -> correct flag
// ---------------------------------------------------------------------------
__global__ void mbe_fin_kernel(float* __restrict__ stats) {
    int i = blockIdx.x * blockDim.x + threadIdx.x;
    if (i < BB * PP) {
        int bi = g_bi[i];
        int b  = i / PP;
        int p  = i - b * PP;
        float c = 0.0f;
        if (bi >= 0 && g_winner[b * GG + bi] == p) c = 1.0f;
        stats[(long)i * 3] = c;
    }
}

// ---------------------------------------------------------------------------
extern "C" void kernel_launch(void* const* d_in, const int* in_sizes, int n_in,
                              void* d_out, int out_size) {
    const float* preds  = (const float*)d_in[0];   // (B,P,6)
    const float* labels = (const float*)d_in[1];   // (B,G,5)
    float* stats    = (float*)d_out;                       // (B,P,3)
    float* out_tcls = (float*)d_out + (long)BB * PP * 3;   // (B,G)

    (void)in_sizes; (void)n_in; (void)out_size;

    int initBlocks = (BB * GG + 255) / 256;
    mbe_init_kernel<<<initBlocks, 256>>>(labels, out_tcls);

    mbe_main_kernel<<<BB * SPLIT, THREADS>>>(preds, labels, stats);

    int finBlocks = (BB * PP + 255) / 256;
    mbe_fin_kernel<<<finBlocks, 256>>>(stats);
}

// round 7
// speedup vs baseline: 1.0007x; 1.0007x over previous
#include <cuda_runtime.h>
#include <climits>

// Problem constants
#define BB 64
#define PP 5000
#define GG 300
#define NC 20
#define SPLIT 10          // chunks per image in the main kernel
#define THREADS 256

// Scratch (device globals -- no allocation allowed)
__device__ int   g_winner[BB * GG];   // min pred index claiming each target
__device__ short g_bi[BB * PP];       // best target per pred, -1 if no candidate

// ---------------------------------------------------------------------------
// Kernel 1: reset winners + write tcls output tail
// out layout assumed: stats (B,P,3) fp32 followed by tcls (B,G) fp32
// ---------------------------------------------------------------------------
__global__ void mbe_init_kernel(const float* __restrict__ labels,
                                float* __restrict__ out_tcls) {
    int i = blockIdx.x * blockDim.x + threadIdx.x;
    if (i < BB * GG) {
        g_winner[i] = INT_MAX;
        out_tcls[i] = labels[i * 5 + 4];   // labels[(b*G+g)*5 + 4]
    }
}

// ---------------------------------------------------------------------------
// Kernel 2: per-pred best-target search with class-bucketed targets.
// grid.x = BB * SPLIT ; each block handles P/SPLIT preds of one image.
// ---------------------------------------------------------------------------
__global__ __launch_bounds__(THREADS)
void mbe_main_kernel(const float* __restrict__ preds,
                     const float* __restrict__ labels,
                     float* __restrict__ stats) {
    __shared__ float  s_lab[GG * 5];
    __shared__ float4 s_tbox[GG];      // scaled (x1,y1,x2,y2), sorted by class
    __shared__ float  s_tarea[GG];
    __shared__ int    s_start[NC + 1];
    __shared__ int    s_cnt[NC];

    const int b     = blockIdx.x / SPLIT;
    const int chunk = blockIdx.x % SPLIT;
    const int tid   = threadIdx.x;

    // Stage labels for this image
    const float* lab = labels + (long)b * GG * 5;
    for (int i = tid; i < GG * 5; i += THREADS) s_lab[i] = lab[i];
    if (tid < NC) s_cnt[tid] = 0;
    __syncthreads();

    // Class histogram
    for (int g = tid; g < GG; g += THREADS) {
        int c = (int)s_lab[g * 5 + 4];
        if ((unsigned)c < NC) atomicAdd(&s_cnt[c], 1);
    }
    __syncthreads();

    if (tid == 0) {
        int acc = 0;
        for (int c = 0; c < NC; c++) { s_start[c] = acc; acc += s_cnt[c]; }
        s_start[NC] = acc;
    }
    __syncthreads();

    // Stable counting-sort placement: one thread per class walks targets in
    // original order -> within-class original order preserved (argmax ties).
    if (tid < NC) {
        int pos = s_start[tid];
        for (int g = 0; g < GG; g++) {
            if ((int)s_lab[g * 5 + 4] == tid) {
                float x1 = s_lab[g * 5 + 0] * 512.0f;
                float y1 = s_lab[g * 5 + 1] * 512.0f;
                float x2 = s_lab[g * 5 + 2] * 512.0f;
                float y2 = s_lab[g * 5 + 3] * 512.0f;
                s_tbox[pos]  = make_float4(x1, y1, x2, y2);
                s_tarea[pos] = (x2 - x1) * (y2 - y1);
                pos++;
            }
        }
    }
    __syncthreads();

    const int winner_base = b * GG;
    const int pper = (PP + SPLIT - 1) / SPLIT;
    const int p0 = chunk * pper;
    const int p1 = (p0 + pper < PP) ? (p0 + pper) : PP;

    for (int p = p0 + tid; p < p1; p += THREADS) {
        const float* pr = preds + ((long)b * PP + p) * 6;
        float2 q0 = *(const float2*)(pr);       // x1, y1
        float2 q1 = *(const float2*)(pr + 2);   // x2, y2
        float2 q2 = *(const float2*)(pr + 4);   // score, cls

        float px1 = q0.x * 512.0f, py1 = q0.y * 512.0f;
        float px2 = q1.x * 512.0f, py2 = q1.y * 512.0f;
        float score = q2.x;
        float fcls  = q2.y;
        float parea = (px2 - px1) * (py2 - py1);
        int cls = (int)fcls;

        int   bi   = -1;
        float best = 0.5f;   // = IOU_THRESH: only > thresh targets can win

        if ((unsigned)cls < NC && score > 0.0f) {
            int t0 = s_start[cls], t1 = s_start[cls + 1];
            for (int t = t0; t < t1; t++) {
                float4 tb = s_tbox[t];
                float lx = fmaxf(px1, tb.x);
                float ly = fmaxf(py1, tb.y);
                float rx = fminf(px2, tb.z);
                float ry = fminf(py2, tb.w);
                float w = fmaxf(rx - lx, 0.0f);
                float h = fmaxf(ry - ly, 0.0f);
                float inter = w * h;
                if (inter > 0.0f) {
                    float denom = (parea + s_tarea[t]) - inter;  // ref op order
                    float iou = __fdiv_rn(inter, denom);          // IEEE div
                    if (iou > best) { best = iou; bi = t; }       // first-max
                }
            }
        }

        g_bi[b * PP + p] = (short)bi;
        if (bi >= 0) atomicMin(&g_winner[winner_base + bi], p);

        long o = ((long)b * PP + p) * 3;
        stats[o + 1] = score;
        stats[o + 2] = fcls;
    }
}

// ---------------------------------------------------------------------------
// Kernel 3: winner check -> correct flag
// ---------------------------------------------------------------------------
__global__ void mbe_fin_kernel(float* __restrict__ stats) {
    int i = blockIdx.x * blockDim.x + threadIdx.x;
    if (i < BB * PP) {
        int bi = g_bi[i];
        int b  = i / PP;
        int p  = i - b * PP;
        float c = 0.0f;
        if (bi >= 0 && g_winner[b * GG + bi] == p) c = 1.0f;
        stats[(long)i * 3] = c;
    }
}

// ---------------------------------------------------------------------------
extern "C" void kernel_launch(void* const* d_in, const int* in_sizes, int n_in,
                              void* d_out, int out_size) {
    const float* preds  = (const float*)d_in[0];   // (B,P,6)
    const float* labels = (const float*)d_in[1];   // (B,G,5)
    float* stats    = (float*)d_out;                       // (B,P,3)
    float* out_tcls = (float*)d_out + (long)BB * PP * 3;   // (B,G)

    (void)in_sizes; (void)n_in; (void)out_size;

    int initBlocks = (BB * GG + 255) / 256;
    mbe_init_kernel<<<initBlocks, 256>>>(labels, out_tcls);

    mbe_main_kernel<<<BB * SPLIT, THREADS>>>(preds, labels, stats);

    int finBlocks = (BB * PP + 255) / 256;
    mbe_fin_kernel<<<finBlocks, 256>>>(stats);
}